// round 1
// baseline (speedup 1.0000x reference)
#include <cuda_runtime.h>
#include <cstdint>

// Problem constants (fixed by the reference)
#define N_CLASSES 50000
#define EMBED_DIM 128
#define N_TOKENS  2048

// Scratch for the per-token class index. __device__ global: allocation-free.
__device__ int g_token_class[N_TOKENS];

// ---------------------------------------------------------------------------
// Kernel 1: scan the dense one-hot matrix [N_CLASSES, N_TOKENS] (row-major,
// fp32) and record, for each token column n, the class row c whose entry is
// nonzero. Exactly one writer per token -> plain store, no atomics.
//
// Each thread reads one uint4 (4 fp32). Total float4 count:
//   N_CLASSES * N_TOKENS / 4 = 50000 * 512 = 25,600,000  -> 100,000 blocks.
// Integer compare vs 0 is valid: one_hot produces exact 0.0f (0x00000000)
// and 1.0f; never -0.0.
// ---------------------------------------------------------------------------
__global__ void __launch_bounds__(256) onehot_scan_kernel(
    const uint4* __restrict__ types_v4, int* __restrict__ token_class)
{
    const unsigned int i = blockIdx.x * 256u + threadIdx.x;   // float4 index
    const uint4 v = types_v4[i];

    if ((v.x | v.y | v.z | v.w) != 0u) {
        // float4s per row = N_TOKENS/4 = 512
        const int c = (int)(i >> 9);              // class row
        const int n = (int)(i & 511u) << 2;       // token column (base of 4)
        if (v.x) token_class[n + 0] = c;
        if (v.y) token_class[n + 1] = c;
        if (v.z) token_class[n + 2] = c;
        if (v.w) token_class[n + 3] = c;
    }
}

// ---------------------------------------------------------------------------
// Kernel 2: gather. out[n, d] = lookup_table[d, idx[n]]
//   lookup_table: [EMBED_DIM, N_CLASSES] row-major
//   out:          [N_TOKENS, EMBED_DIM] row-major (coalesced writes)
// One block per token, one thread per embed dim.
// ---------------------------------------------------------------------------
__global__ void __launch_bounds__(EMBED_DIM) embed_gather_kernel(
    const float* __restrict__ lookup_table,
    const int*   __restrict__ token_class,
    float*       __restrict__ out)
{
    const int n = blockIdx.x;
    const int d = threadIdx.x;
    const int c = token_class[n];                 // broadcast within block
    out[n * EMBED_DIM + d] = lookup_table[(size_t)d * N_CLASSES + c];
}

extern "C" void kernel_launch(void* const* d_in, const int* in_sizes, int n_in,
                              void* d_out, int out_size)
{
    // Resolve inputs by size: types has 102,400,000 elems, lookup 6,400,000.
    const float* types  = (const float*)d_in[0];
    const float* lookup = (const float*)d_in[1];
    if (n_in >= 2 && in_sizes[0] == EMBED_DIM * N_CLASSES &&
        in_sizes[1] == N_CLASSES * N_TOKENS) {
        const float* t = types; types = lookup; lookup = t;
    }

    int* token_class;
    cudaGetSymbolAddress((void**)&token_class, g_token_class);

    const unsigned int n_vec4  = (unsigned int)((size_t)N_CLASSES * N_TOKENS / 4);
    const unsigned int nblocks = n_vec4 / 256u;   // 100,000 exactly

    onehot_scan_kernel<<<nblocks, 256>>>((const uint4*)types, token_class);
    embed_gather_kernel<<<N_TOKENS, EMBED_DIM>>>(lookup, token_class, (float*)d_out);
}

// round 3
// speedup vs baseline: 1.1781x; 1.1781x over previous
#include <cuda_runtime.h>
#include <cstdint>

// Problem constants (fixed by the reference)
#define N_CLASSES 50000
#define EMBED_DIM 128
#define N_TOKENS  2048

#define TPB   256                 // threads per block
#define VPT   8                   // float4 vectors per thread
// total float4: N_CLASSES*N_TOKENS/4 = 25,600,000 = 12,500 blocks * 256 * 8
#define NBLOCKS (N_CLASSES * (N_TOKENS / 4) / (TPB * VPT))

// ---------------------------------------------------------------------------
// Rare path: token n's class is c -> gather its 128-dim embedding.
//   out[n, d] = lookup[d * N_CLASSES + c],  d = 0..127
// 128 independent scattered loads, 32 loads in flight (unroll 8), coalesced
// float4 stores. Runs concurrently with the surrounding DRAM stream.
// ---------------------------------------------------------------------------
__device__ __forceinline__ void gather_token(
    const float* __restrict__ lookup, float* __restrict__ out, int c, int n)
{
    const float* __restrict__ src = lookup + c;
    float4* __restrict__ dst = reinterpret_cast<float4*>(out + n * EMBED_DIM);
    #pragma unroll 8
    for (int j = 0; j < EMBED_DIM / 4; ++j) {
        float4 r;
        r.x = src[(size_t)(4 * j + 0) * N_CLASSES];
        r.y = src[(size_t)(4 * j + 1) * N_CLASSES];
        r.z = src[(size_t)(4 * j + 2) * N_CLASSES];
        r.w = src[(size_t)(4 * j + 3) * N_CLASSES];
        dst[j] = r;
    }
}

// ---------------------------------------------------------------------------
// Fused scan + gather over the dense one-hot matrix [N_CLASSES, N_TOKENS]
// (row-major fp32). Each thread streams 8 float4s (blockDim-strided, fully
// coalesced, evict-first). On the rare nonzero hit, the finder thread gathers
// that token's embedding directly. Integer compare vs 0 is exact: one_hot
// yields only 0.0f (0x00000000) and 1.0f, never -0.0.
// ---------------------------------------------------------------------------
__global__ void __launch_bounds__(TPB) onehot_embed_fused_kernel(
    const uint4* __restrict__ types_v4,
    const float* __restrict__ lookup,
    float*       __restrict__ out)
{
    const unsigned int base = blockIdx.x * (TPB * VPT) + threadIdx.x;

    uint4 v[VPT];
    #pragma unroll
    for (int u = 0; u < VPT; ++u)
        v[u] = __ldcs(&types_v4[base + u * TPB]);

    unsigned int any = 0;
    #pragma unroll
    for (int u = 0; u < VPT; ++u)
        any |= v[u].x | v[u].y | v[u].z | v[u].w;

    if (any != 0u) {                              // rare: ~2048 / 3.2M threads
        #pragma unroll
        for (int u = 0; u < VPT; ++u) {
            if ((v[u].x | v[u].y | v[u].z | v[u].w) != 0u) {
                const unsigned int i = base + u * TPB;   // float4 index
                const int c = (int)(i >> 9);             // class row (512 f4/row)
                const int n = (int)(i & 511u) << 2;      // token col base
                if (v[u].x) gather_token(lookup, out, c, n + 0);
                if (v[u].y) gather_token(lookup, out, c, n + 1);
                if (v[u].z) gather_token(lookup, out, c, n + 2);
                if (v[u].w) gather_token(lookup, out, c, n + 3);
            }
        }
    }
}

extern "C" void kernel_launch(void* const* d_in, const int* in_sizes, int n_in,
                              void* d_out, int out_size)
{
    // Resolve inputs by size: types has 102,400,000 elems, lookup 6,400,000.
    const float* types  = (const float*)d_in[0];
    const float* lookup = (const float*)d_in[1];
    if (n_in >= 2 && in_sizes[0] == EMBED_DIM * N_CLASSES &&
        in_sizes[1] == N_CLASSES * N_TOKENS) {
        const float* t = types; types = lookup; lookup = t;
    }

    onehot_embed_fused_kernel<<<NBLOCKS, TPB>>>(
        (const uint4*)types, lookup, (float*)d_out);
}